// round 12
// baseline (speedup 1.0000x reference)
#include <cuda_runtime.h>
#include <stdint.h>

// Problem shape (fixed by the reference): x is (T, B, 1) fp32, lr scalar.
#define T_DIM 8192
#define B_DIM 4096
#define S_CHUNKS 64
#define HALF (S_CHUNKS / 2)   // 32 chunks per half
#define CH 128                // T_DIM / S_CHUNKS
#define NWORDS 4              // CH / 32

// Scratch (device globals). Chunk-major, coalesced over b.
__device__ float4 g_coef [S_CHUNKS * B_DIM];        // (A0,C0,A1,C1)       4 MB
__device__ uint4  g_bits [S_CHUNKS * B_DIM];        // 128 packed x bits   4 MB
__device__ float  g_xprev[S_CHUNKS * B_DIM];        // x[t0-1]             1 MB
__device__ float2 g_state[(S_CHUNKS + 1) * B_DIM];  // entry (p0,p1); +1 hand-off

__device__ __forceinline__ float clamp_lr(const float* lrp) {
    return fminf(fmaxf(*lrp, 0.0f), 1.0f);
}

// r^n, n in [0,128], square-and-multiply (no smem, no syncs).
__device__ __forceinline__ float rpow_int(float r, int n) {
    float res = 1.0f, base = r;
    #pragma unroll
    for (int i = 0; i < 8; i++) {
        res  = ((n >> i) & 1) ? res * base : res;
        base = base * base;
    }
    return res;
}

// ---------------------------------------------------------------------------
// Pass-1 body (R4 math, plain LDG): stream one x chunk, pack bits to regs,
// emit affine (A,C) via the popcount trick.
// ---------------------------------------------------------------------------
__device__ __forceinline__ void pass1_body(
    const float* __restrict__ x, float lr, float r, int s, int b)
{
    const float* xp = x + (size_t)(s * CH) * B_DIM + b;

    const float xprev = (s == 0) ? 0.0f : xp[-(ptrdiff_t)B_DIM];
    g_xprev[s * B_DIM + b] = xprev;
    bool pb = (xprev != 0.0f);

    float C0 = 0.0f, C1 = 0.0f;
    uint32_t W[NWORDS];

    #pragma unroll
    for (int h = 0; h < NWORDS; h++) {
        uint32_t w = 0;
        #pragma unroll
        for (int i0 = 0; i0 < 32; i0 += 8) {
            float xv[8];                               // 8-deep LDG batch
            #pragma unroll
            for (int j = 0; j < 8; j++)
                xv[j] = xp[(size_t)(h * 32 + i0 + j) * B_DIM];
            #pragma unroll
            for (int j = 0; j < 8; j++) {
                const float v  = xv[j];
                const bool  xb = (v != 0.0f);
                const float t  = v * lr;               // exact: x in {0,1}
                C0 = pb ? C0 : fmaf(C0, r, t);
                C1 = pb ? fmaf(C1, r, t) : C1;
                w  = xb ? (w | (1u << (i0 + j))) : w;
                pb = xb;
            }
        }
        W[h] = w;
    }

    const int ones = __popc(W[0]) + __popc(W[1]) + __popc(W[2]) + __popc(W[3]);
    const int n1   = ones - (int)(W[3] >> 31) + (xprev != 0.0f ? 1 : 0);

    g_coef[s * B_DIM + b] = make_float4(rpow_int(r, CH - n1), C0,
                                        rpow_int(r, n1),      C1);
    g_bits[s * B_DIM + b] = make_uint4(W[0], W[1], W[2], W[3]);
}

// ---------------------------------------------------------------------------
// Pass-2 body (R10 lean step — proven): selected/other representation,
// ~7 instructions per output including the store.
// ---------------------------------------------------------------------------
__device__ __forceinline__ void pass2_body(
    float* __restrict__ out, float lr, float r, int s, int b)
{
    float* op = out + (size_t)(s * CH) * B_DIM + b;

    const float2 st = g_state[s * B_DIM + b];
    const uint4  bw = g_bits [s * B_DIM + b];
    const uint32_t W[NWORDS] = { bw.x, bw.y, bw.z, bw.w };
    bool pb = (g_xprev[s * B_DIM + b] != 0.0f);

    float pa = pb ? st.y : st.x;     // selected lineage
    float po = pb ? st.x : st.y;     // other lineage

    #pragma unroll
    for (int wi = 0; wi < NWORDS; wi++) {
        const uint32_t w = W[wi];
        #pragma unroll
        for (int i = 0; i < 32; i++) {
            const bool  xb  = (w >> i) & 1u;
            const float add = xb ? lr : 0.0f;
            const float u   = fmaf(r, pa, add);
            const bool  sw  = (xb == pb);
            const float npa = sw ? u  : po;
            po              = sw ? po : u;
            pa = npa;
            op[(size_t)(wi * 32 + i) * B_DIM] = pa;   // output == next selected
            pb = xb;
        }
    }
}

// ---------------------------------------------------------------------------
// Stage kernels.
// ---------------------------------------------------------------------------
__global__ void __launch_bounds__(256) p1_kernel(
    const float* __restrict__ x, const float* __restrict__ lrp, int s_base)
{
    const int b = blockIdx.x * blockDim.x + threadIdx.x;
    const float lr = clamp_lr(lrp);
    pass1_body(x, lr, 1.0f - lr, s_base + blockIdx.y, b);
}

__global__ void __launch_bounds__(256) p2_kernel(
    float* __restrict__ out, const float* __restrict__ lrp, int s_base)
{
    const int b = blockIdx.x * blockDim.x + threadIdx.x;
    const float lr = clamp_lr(lrp);
    pass2_body(out, lr, 1.0f - lr, s_base + blockIdx.y, b);
}

// Mixed grid: even blockIdx.y -> pass2 on H1 chunk y/2 (writes),
//             odd  blockIdx.y -> pass1 on H2 chunk 32+y/2 (reads).
// Interleaved dispatch keeps both HBM directions active simultaneously.
__global__ void __launch_bounds__(256) mixed_kernel(
    const float* __restrict__ x, float* __restrict__ out,
    const float* __restrict__ lrp)
{
    const int b = blockIdx.x * blockDim.x + threadIdx.x;
    const float lr = clamp_lr(lrp);
    const float r  = 1.0f - lr;
    const int y = blockIdx.y;
    if (y & 1) pass1_body(x, lr, r, HALF + (y >> 1), b);
    else       pass2_body(out, lr, r, (y >> 1), b);
}

// Partial scan with COMPILE-TIME bounds (R11's runtime bounds broke the
// 8-deep load batching -> 19.7us; template restores R4's proven codegen).
template <int SB, int SE, bool INIT>
__global__ void __launch_bounds__(256) scan_tpl()
{
    const int b = blockIdx.x * blockDim.x + threadIdx.x;
    float p0, p1;
    if (INIT) { p0 = 0.5f; p1 = 0.5f; }
    else      { const float2 h = g_state[SB * B_DIM + b]; p0 = h.x; p1 = h.y; }

    #pragma unroll 8
    for (int s = SB; s < SE; s++) {
        g_state[s * B_DIM + b] = make_float2(p0, p1);
        const float4 c = g_coef[s * B_DIM + b];
        p0 = fmaf(p0, c.x, c.y);
        p1 = fmaf(p1, c.z, c.w);
    }
    g_state[SE * B_DIM + b] = make_float2(p0, p1);   // hand-off
}

extern "C" void kernel_launch(void* const* d_in, const int* in_sizes, int n_in,
                              void* d_out, int out_size)
{
    const float* x  = (const float*)d_in[0];
    const float* lr = (const float*)d_in[1];
    if (n_in >= 2 && in_sizes[0] == 1) { x = (const float*)d_in[1]; lr = (const float*)d_in[0]; }
    float* out = (float*)d_out;

    dim3 blk(256);
    dim3 grid_half (B_DIM / 256, HALF);       // (16, 32)
    dim3 grid_mixed(B_DIM / 256, S_CHUNKS);   // (16, 64): 512 p2 + 512 p1 blocks
    dim3 grid_scan (B_DIM / 256);

    p1_kernel<<<grid_half, blk>>>(x, lr, 0);               // read H1
    scan_tpl<0, HALF, true><<<grid_scan, blk>>>();         // states 0..31 + hand-off
    mixed_kernel<<<grid_mixed, blk>>>(x, out, lr);         // write H1 || read H2
    scan_tpl<HALF, S_CHUNKS, false><<<grid_scan, blk>>>(); // states 32..63
    p2_kernel<<<grid_half, blk>>>(out, lr, HALF);          // write H2
}

// round 13
// speedup vs baseline: 1.1624x; 1.1624x over previous
#include <cuda_runtime.h>
#include <stdint.h>

// Problem shape (fixed by the reference): x is (T, B, 1) fp32, lr scalar.
#define T_DIM 8192
#define B_DIM 4096
#define S_CHUNKS 64
#define CH 128          // T_DIM / S_CHUNKS
#define NWORDS 4        // CH / 32

// Scratch (device globals). Chunk-major, coalesced over b.
__device__ float4 g_coef [S_CHUNKS * B_DIM];  // (A0, C0, A1, C1) per (s,b)   4 MB
__device__ uint4  g_bits [S_CHUNKS * B_DIM];  // 128 packed x bits per (s,b)  4 MB
__device__ float  g_xprev[S_CHUNKS * B_DIM];  // x[t0-1] per (s,b)            1 MB
__device__ float2 g_state[S_CHUNKS * B_DIM];  // (p0,p1) entering chunk       2 MB

__device__ __forceinline__ float clamp_lr(const float* lrp) {
    return fminf(fmaxf(*lrp, 0.0f), 1.0f);
}

// r^n, n in [0,128], square-and-multiply (no smem, no syncs).
__device__ __forceinline__ float rpow_int(float r, int n) {
    float res = 1.0f, base = r;
    #pragma unroll
    for (int i = 0; i < 8; i++) {
        res  = ((n >> i) & 1) ? res * base : res;
        base = base * base;
    }
    return res;
}

// ---------------------------------------------------------------------------
// Pass 1 (R4 verbatim — best measured, 27.1us): per (chunk s, column b), one
// column per thread (262144 threads, ~55 warps/SM). Streams x once with plain
// LDG (caching variant measured faster than __ldcs: fewer registers, higher
// occupancy). Bits packed to registers; chunk multiplier A = r^(#updates)
// via popcount of the obs_prev bit stream; additive C term per-step FMA.
// ---------------------------------------------------------------------------
__global__ void __launch_bounds__(256) pass1_kernel(
    const float* __restrict__ x, const float* __restrict__ lrp)
{
    const int b = blockIdx.x * blockDim.x + threadIdx.x;
    const int s = blockIdx.y;
    const float lr = clamp_lr(lrp);
    const float r  = 1.0f - lr;

    const float* xp = x + (size_t)(s * CH) * B_DIM + b;

    const float xprev = (s == 0) ? 0.0f : xp[-(ptrdiff_t)B_DIM];
    g_xprev[s * B_DIM + b] = xprev;
    bool pb = (xprev != 0.0f);

    float C0 = 0.0f, C1 = 0.0f;
    uint32_t W[NWORDS];

    #pragma unroll
    for (int h = 0; h < NWORDS; h++) {
        uint32_t w = 0;
        #pragma unroll
        for (int i0 = 0; i0 < 32; i0 += 8) {
            float xv[8];                               // 8-deep LDG batch
            #pragma unroll
            for (int j = 0; j < 8; j++)
                xv[j] = xp[(size_t)(h * 32 + i0 + j) * B_DIM];
            #pragma unroll
            for (int j = 0; j < 8; j++) {
                const float v  = xv[j];
                const bool  xb = (v != 0.0f);
                const float t  = v * lr;               // exact: x in {0,1}
                C0 = pb ? C0 : fmaf(C0, r, t);
                C1 = pb ? fmaf(C1, r, t) : C1;
                w  = xb ? (w | (1u << (i0 + j))) : w;
                pb = xb;
            }
        }
        W[h] = w;
    }

    // obs_prev stream over the chunk = [xprev, x_0 .. x_126]
    const int ones = __popc(W[0]) + __popc(W[1]) + __popc(W[2]) + __popc(W[3]);
    const int n1   = ones - (int)(W[3] >> 31) + (xprev != 0.0f ? 1 : 0);

    g_coef[s * B_DIM + b] = make_float4(rpow_int(r, CH - n1), C0,
                                        rpow_int(r, n1),      C1);
    g_bits[s * B_DIM + b] = make_uint4(W[0], W[1], W[2], W[3]);
}

// ---------------------------------------------------------------------------
// Scan (R4 verbatim): one thread per column; 64 sequential affine
// compositions. coef data is L2-resident after pass1 in the real (unflushed)
// run, so this costs ~3.5us. Stores (p0,p1) entering each chunk.
// ---------------------------------------------------------------------------
__global__ void __launch_bounds__(256) scan_kernel()
{
    const int b = blockIdx.x * blockDim.x + threadIdx.x;
    float p0 = 0.5f, p1 = 0.5f;
    #pragma unroll 8
    for (int s = 0; s < S_CHUNKS; s++) {
        const float4 c = g_coef[s * B_DIM + b];
        g_state[s * B_DIM + b] = make_float2(p0, p1);
        p0 = fmaf(p0, c.x, c.y);
        p1 = fmaf(p1, c.z, c.w);
    }
}

// ---------------------------------------------------------------------------
// Pass 2 (R10 lean step — best measured of five variants): selected/other
// representation. pa = lineage selected by pb, po = the other; the step's
// output IS the next step's selected state:
//   u  = fma(r, pa, xb ? lr : 0)   ; sw = (xb == pb)
//   pa' = sw ? u : po ; po' = sw ? po : u ; store pa'
// ~7 instructions per output including the store.
// ---------------------------------------------------------------------------
__global__ void __launch_bounds__(256) pass2_kernel(
    float* __restrict__ out, const float* __restrict__ lrp)
{
    const int b = blockIdx.x * blockDim.x + threadIdx.x;
    const int s = blockIdx.y;
    const float lr = clamp_lr(lrp);
    const float r  = 1.0f - lr;

    float* op = out + (size_t)(s * CH) * B_DIM + b;

    const float2 st = g_state[s * B_DIM + b];
    const uint4  bw = g_bits [s * B_DIM + b];
    const uint32_t W[NWORDS] = { bw.x, bw.y, bw.z, bw.w };
    bool pb = (g_xprev[s * B_DIM + b] != 0.0f);

    float pa = pb ? st.y : st.x;     // selected lineage
    float po = pb ? st.x : st.y;     // other lineage

    #pragma unroll
    for (int wi = 0; wi < NWORDS; wi++) {
        const uint32_t w = W[wi];
        #pragma unroll
        for (int i = 0; i < 32; i++) {
            const bool  xb  = (w >> i) & 1u;
            const float add = xb ? lr : 0.0f;
            const float u   = fmaf(r, pa, add);
            const bool  sw  = (xb == pb);
            const float npa = sw ? u  : po;
            po              = sw ? po : u;
            pa = npa;
            op[(size_t)(wi * 32 + i) * B_DIM] = pa;   // output == next selected
            pb = xb;
        }
    }
}

extern "C" void kernel_launch(void* const* d_in, const int* in_sizes, int n_in,
                              void* d_out, int out_size)
{
    const float* x  = (const float*)d_in[0];
    const float* lr = (const float*)d_in[1];
    if (n_in >= 2 && in_sizes[0] == 1) { x = (const float*)d_in[1]; lr = (const float*)d_in[0]; }

    dim3 blk(256);

    pass1_kernel<<<dim3(B_DIM / 256, S_CHUNKS), blk>>>(x, lr);
    scan_kernel<<<B_DIM / 256, blk>>>();
    pass2_kernel<<<dim3(B_DIM / 256, S_CHUNKS), blk>>>((float*)d_out, lr);
}